// round 3
// baseline (speedup 1.0000x reference)
#include <cuda_runtime.h>
#include <cstdint>
#include <cstddef>

#define TT_T 256      // tokens
#define HH 1024       // hidden
#define EE 256        // experts
#define II 256        // intermediate
#define NPAIR 2048    // T * top_k

typedef unsigned long long u64;

// ---------------- scratch (device globals; no allocations allowed) ----------------
__device__ float g_scores[TT_T * EE];        // sigmoid(logits)
__device__ int   g_cnt[EE];
__device__ int   g_base[EE];
__device__ int   g_pair_tok[NPAIR];
__device__ float g_pair_w[NPAIR];

// ---------------- f32x2 helpers ----------------
__device__ __forceinline__ u64 fma2(u64 a, u64 b, u64 c) {
    u64 d;
    asm("fma.rn.f32x2 %0, %1, %2, %3;" : "=l"(d) : "l"(a), "l"(b), "l"(c));
    return d;
}
__device__ __forceinline__ u64 add2(u64 a, u64 b) {
    u64 d;
    asm("add.rn.f32x2 %0, %1, %2;" : "=l"(d) : "l"(a), "l"(b));
    return d;
}
__device__ __forceinline__ u64 pack2(float x, float y) {
    u64 r;
    asm("mov.b64 %0, {%1, %2};" : "=l"(r) : "f"(x), "f"(y));
    return r;
}
__device__ __forceinline__ float2 unpack2(u64 v) {
    float2 r;
    asm("mov.b64 {%0, %1}, %2;" : "=f"(r.x), "=f"(r.y) : "l"(v));
    return r;
}

// ---------------- kernel: zero output ----------------
__global__ void k_zero(float* __restrict__ out, int n) {
    int i = blockIdx.x * blockDim.x + threadIdx.x;
    if (i < n) out[i] = 0.f;
}

// ---------------- kernel: gate scores = sigmoid(x @ gate_w^T) ----------------
__global__ void k_gate(const float* __restrict__ x, const float* __restrict__ gw) {
    __shared__ float gws[8 * HH];
    int eg = blockIdx.x & 31;
    int tg = blockIdx.x >> 5;
    int tid = threadIdx.x;
    for (int idx = tid; idx < 8 * HH; idx += 256)
        gws[idx] = gw[eg * 8 * HH + idx];
    __syncthreads();
    int warp = tid >> 5, lane = tid & 31;
    for (int tt = warp; tt < 32; tt += 8) {
        int t = tg * 32 + tt;
        float acc[8];
#pragma unroll
        for (int e = 0; e < 8; e++) acc[e] = 0.f;
        for (int h = lane; h < HH; h += 32) {
            float xv = x[t * HH + h];
#pragma unroll
            for (int e = 0; e < 8; e++) acc[e] += xv * gws[e * HH + h];
        }
#pragma unroll
        for (int e = 0; e < 8; e++) {
            float v = acc[e];
#pragma unroll
            for (int s = 16; s > 0; s >>= 1) v += __shfl_xor_sync(0xffffffffu, v, s);
            if (lane == e)
                g_scores[t * EE + eg * 8 + e] = 1.f / (1.f + __expf(-v));
        }
    }
}

// ---------------- kernel: routing (1 block, thread = token) ----------------
__global__ void k_route(const float* __restrict__ e_bias) {
    int t = threadIdx.x;
    __shared__ float s_bias[EE];
    __shared__ int s_cnt[EE];
    __shared__ int s_ofs[EE];
    s_bias[t] = e_bias[t];
    s_cnt[t] = 0;
    __syncthreads();
    const float* srow = g_scores + t * EE;

    float gsum[8];
#pragma unroll
    for (int g = 0; g < 8; g++) {
        float m1 = -1e30f, m2 = -1e30f;
        for (int j = 0; j < 32; j++) {
            float v = srow[g * 32 + j] + s_bias[g * 32 + j];
            if (v > m1) { m2 = m1; m1 = v; }
            else if (v > m2) { m2 = v; }
        }
        gsum[g] = m1 + m2;
    }
    unsigned gmask = 0;
    for (int it = 0; it < 4; it++) {
        float best = -1e30f; int bi = 0;
#pragma unroll
        for (int g = 0; g < 8; g++)
            if (!((gmask >> g) & 1u) && gsum[g] > best) { best = gsum[g]; bi = g; }
        gmask |= 1u << bi;
    }
    float bv[8]; int bidx[8];
#pragma unroll
    for (int k = 0; k < 8; k++) { bv[k] = -1e30f; bidx[k] = -1; }
    for (int g = 0; g < 8; g++) {
        if (!((gmask >> g) & 1u)) continue;
        for (int j = 0; j < 32; j++) {
            int e = g * 32 + j;
            float v = srow[e] + s_bias[e];
            if (v > bv[7]) {
#pragma unroll
                for (int k = 7; k > 0; k--) {
                    bool sh = v > bv[k - 1];
                    bool ins = (v > bv[k]) && !sh;
                    float nv = sh ? bv[k - 1] : (ins ? v : bv[k]);
                    int   ni = sh ? bidx[k - 1] : (ins ? e : bidx[k]);
                    bv[k] = nv; bidx[k] = ni;
                }
                if (v > bv[0]) { bv[0] = v; bidx[0] = e; }
            }
        }
    }
    float w[8]; float wsum = 0.f;
#pragma unroll
    for (int k = 0; k < 8; k++) { w[k] = srow[bidx[k]]; wsum += w[k]; }
    float scl = 2.5f / (wsum + 1e-20f);
#pragma unroll
    for (int k = 0; k < 8; k++) {
        w[k] *= scl;
        atomicAdd(&s_cnt[bidx[k]], 1);
    }
    __syncthreads();
    int base = 0;
    for (int e = 0; e < t; e++) base += s_cnt[e];
    s_ofs[t] = base;
    g_base[t] = base;
    g_cnt[t] = s_cnt[t];
    __syncthreads();
#pragma unroll
    for (int k = 0; k < 8; k++) {
        int slot = atomicAdd(&s_ofs[bidx[k]], 1);
        g_pair_tok[slot] = t;
        g_pair_w[slot] = w[k];
    }
}

// ---------------- fused expert tile: mlp1 (gate/up + silu*up) then down ----------------
// 256 threads. mlp1: ip = tid&127 owns i-pair, hs = tid>>7 slices h (2 slices).
// Weight loads double-buffered with prefetch across h-chunk boundaries.
// act kept in smem (dup f32x2). down: 2 passes, thread owns (h-pair, chunk), atomics to out.
template <int TT>
__device__ __forceinline__ void moe_tile(
    const float* __restrict__ x,
    const float* __restrict__ wg, const float* __restrict__ wu,
    const float* __restrict__ wd,
    const int* s_toks, const float* s_w, int nt,
    u64* xs, float* __restrict__ out)
{
    const int tid = threadIdx.x;
    const int ip = tid & 127;
    const int hs = tid >> 7;
    const float2* wg2 = (const float2*)wg;
    const float2* wu2 = (const float2*)wu;

    u64 ag[TT], au[TT];
#pragma unroll
    for (int t2 = 0; t2 < TT; t2++) { ag[t2] = 0ull; au[t2] = 0ull; }

    float2 wa[2][4], wb[2][4];
    // prologue: prefetch step 0 weights (independent of x staging)
    {
        int hg = hs * 4;
#pragma unroll
        for (int u = 0; u < 4; u++) {
            wa[0][u] = wg2[(size_t)(hg + u) * 128 + ip];
            wb[0][u] = wu2[(size_t)(hg + u) * 128 + ip];
        }
    }

    // 128 steps: step s covers global h = (s>>5)*256 + hs*4 + (s&31)*8 .. +3
#pragma unroll 1
    for (int s = 0; s < 128; s++) {
        if ((s & 31) == 0) {
            int h0 = (s >> 5) * 256;
            __syncthreads();
            for (int idx = tid; idx < TT * 256; idx += 256) {
                int t2 = idx >> 8;
                int h = idx & 255;
                float v = (t2 < nt) ? __ldg(&x[s_toks[t2] * HH + h0 + h]) : 0.f;
                xs[idx] = pack2(v, v);
            }
            __syncthreads();
        }
        const int cur = s & 1, nxt = cur ^ 1;
        if (s + 1 < 128) {
            int s1 = s + 1;
            int hg = (s1 >> 5) * 256 + hs * 4 + (s1 & 31) * 8;
#pragma unroll
            for (int u = 0; u < 4; u++) {
                wa[nxt][u] = wg2[(size_t)(hg + u) * 128 + ip];
                wb[nxt][u] = wu2[(size_t)(hg + u) * 128 + ip];
            }
        }
        const int hl = hs * 4 + (s & 31) * 8;
#pragma unroll
        for (int u = 0; u < 4; u++) {
            u64 wgp = pack2(wa[cur][u].x, wa[cur][u].y);
            u64 wup = pack2(wb[cur][u].x, wb[cur][u].y);
#pragma unroll
            for (int t2 = 0; t2 < TT; t2++) {
                u64 xv = xs[t2 * 256 + hl + u];
                ag[t2] = fma2(xv, wgp, ag[t2]);
                au[t2] = fma2(xv, wup, au[t2]);
            }
        }
    }

    // ---- cross-slice reduce (2 slices) + silu, act -> xs as dup f32x2 [t2*256 + i] ----
    __syncthreads();
#pragma unroll
    for (int t2 = 0; t2 < TT; t2++) xs[t2 * 256 + hs * 128 + ip] = ag[t2];
    __syncthreads();
    u64 agsum[TT];
    if (hs == 0) {
#pragma unroll
        for (int t2 = 0; t2 < TT; t2++)
            agsum[t2] = add2(xs[t2 * 256 + ip], xs[t2 * 256 + 128 + ip]);
    }
    __syncthreads();
#pragma unroll
    for (int t2 = 0; t2 < TT; t2++) xs[t2 * 256 + hs * 128 + ip] = au[t2];
    __syncthreads();
    u64 ausum[TT];
    if (hs == 0) {
#pragma unroll
        for (int t2 = 0; t2 < TT; t2++)
            ausum[t2] = add2(xs[t2 * 256 + ip], xs[t2 * 256 + 128 + ip]);
    }
    __syncthreads();   // all reads of au slices done before act overwrites
    if (hs == 0) {
#pragma unroll
        for (int t2 = 0; t2 < TT; t2++) {
            float2 g = unpack2(agsum[t2]);
            float2 u = unpack2(ausum[t2]);
            float a0 = g.x / (1.f + __expf(-g.x)) * u.x;
            float a1 = g.y / (1.f + __expf(-g.y)) * u.y;
            xs[t2 * 256 + 2 * ip]     = pack2(a0, a0);
            xs[t2 * 256 + 2 * ip + 1] = pack2(a1, a1);
        }
    }
    __syncthreads();

    // ---- down: thread owns (h-pair hcol, chunk), 2 sequential passes ----
    const float2* wd2 = (const float2*)wd;
#pragma unroll 1
    for (int p = 0; p < 2; p++) {
        const int c = hs + 2 * p;
        const int hcol = c * 128 + ip;     // h-pair 0..511
        u64 acc[TT];
#pragma unroll
        for (int t2 = 0; t2 < TT; t2++) acc[t2] = 0ull;
        float2 wv[2][4];
#pragma unroll
        for (int u = 0; u < 4; u++) wv[0][u] = wd2[(size_t)u * 512 + hcol];
#pragma unroll 1
        for (int s = 0; s < 64; s++) {
            const int cur = s & 1, nxt = cur ^ 1;
            if (s + 1 < 64) {
#pragma unroll
                for (int u = 0; u < 4; u++)
                    wv[nxt][u] = wd2[(size_t)((s + 1) * 4 + u) * 512 + hcol];
            }
#pragma unroll
            for (int u = 0; u < 4; u++) {
                u64 wp = pack2(wv[cur][u].x, wv[cur][u].y);
#pragma unroll
                for (int t2 = 0; t2 < TT; t2++)
                    acc[t2] = fma2(xs[t2 * 256 + s * 4 + u], wp, acc[t2]);
            }
        }
#pragma unroll
        for (int t2 = 0; t2 < TT; t2++) {
            if (t2 < nt) {
                float2 r = unpack2(acc[t2]);
                float w = s_w[t2];
                int tok = s_toks[t2];
                atomicAdd(out + (size_t)tok * HH + 2 * hcol,     w * r.x);
                atomicAdd(out + (size_t)tok * HH + 2 * hcol + 1, w * r.y);
            }
        }
    }
}

// grid = EE (tile 0) + 16 shared tiles + EE (tile 1, usually empty); 256 threads
__global__ void __launch_bounds__(256, 2) k_moe(
    const float* __restrict__ x,
    const float* __restrict__ wgate, const float* __restrict__ wup,
    const float* __restrict__ wdown,
    const float* __restrict__ swg, const float* __restrict__ swu,
    const float* __restrict__ swd,
    float* __restrict__ out)
{
    __shared__ u64 xs[16 * 256];    // 32 KB: x stage -> reduce scratch -> act
    __shared__ int s_toks[16];
    __shared__ float s_w[16];
    int b = blockIdx.x;
    if (b < EE || b >= EE + 16) {
        int e    = (b < EE) ? b : (b - EE - 16);
        int off0 = (b < EE) ? 0 : 16;
        int cnt = g_cnt[e];
        if (off0 >= cnt) return;
        int base = g_base[e];
        const float* wg = wgate + (size_t)e * HH * II;
        const float* wu = wup   + (size_t)e * HH * II;
        const float* wd = wdown + (size_t)e * II * HH;
        for (int off = off0; off < cnt; off += 32) {
            int nt = min(cnt - off, 16);
            __syncthreads();
            if (threadIdx.x < nt) {
                s_toks[threadIdx.x] = g_pair_tok[base + off + threadIdx.x];
                s_w[threadIdx.x]    = g_pair_w[base + off + threadIdx.x];
            }
            if (nt <= 8) moe_tile<8>(x, wg, wu, wd, s_toks, s_w, nt, xs, out);
            else         moe_tile<16>(x, wg, wu, wd, s_toks, s_w, nt, xs, out);
        }
    } else {
        int j = b - EE;
        if (threadIdx.x < 16) {
            s_toks[threadIdx.x] = j * 16 + threadIdx.x;
            s_w[threadIdx.x] = 1.0f;
        }
        moe_tile<16>(x, swg, swu, swd, s_toks, s_w, 16, xs, out);
    }
}

// ---------------- launch ----------------
extern "C" void kernel_launch(void* const* d_in, const int* in_sizes, int n_in,
                              void* d_out, int out_size)
{
    const float* x       = (const float*)d_in[0];  // [1,1,T,H]
    const float* gate_w  = (const float*)d_in[1];  // [E,H]
    const float* e_bias  = (const float*)d_in[2];  // [E]
    const float* w_gate  = (const float*)d_in[3];  // [E,H,I]
    const float* w_up    = (const float*)d_in[4];  // [E,H,I]
    const float* w_down  = (const float*)d_in[5];  // [E,I,H]
    const float* sw_gate = (const float*)d_in[6];  // [H,I]
    const float* sw_up   = (const float*)d_in[7];  // [H,I]
    const float* sw_down = (const float*)d_in[8];  // [I,H]
    float* out = (float*)d_out;                    // [1,1,T,H] fp32

    k_zero<<<(TT_T * HH + 255) / 256, 256>>>(out, TT_T * HH);
    k_gate<<<256, 256>>>(x, gate_w);
    k_route<<<1, 256>>>(e_bias);
    k_moe<<<EE * 2 + 16, 256>>>(x, w_gate, w_up, w_down,
                                sw_gate, sw_up, sw_down, out);
}

// round 4
// speedup vs baseline: 1.2729x; 1.2729x over previous
#include <cuda_runtime.h>
#include <cstdint>
#include <cstddef>

#define TT_T 256      // tokens
#define HH 1024       // hidden
#define EE 256        // experts
#define II 256        // intermediate
#define NPAIR 2048    // T * top_k

// ---------------- scratch (device globals; no allocations allowed) ----------------
__device__ float g_scores[TT_T * EE];        // sigmoid(logits)
__device__ int   g_cnt[EE];
__device__ int   g_base[EE];
__device__ int   g_pair_tok[NPAIR];
__device__ float g_pair_w[NPAIR];
__device__ float g_act[NPAIR * II];          // routed silu(h1)*h3
__device__ float g_act_sh[TT_T * II];        // shared-expert silu(h1)*h3

// ---------------- kernel: zero output ----------------
__global__ void k_zero(float* __restrict__ out, int n) {
    int i = blockIdx.x * blockDim.x + threadIdx.x;
    if (i < n) out[i] = 0.f;
}

// ---------------- kernel: gate scores = sigmoid(x @ gate_w^T) ----------------
__global__ void k_gate(const float* __restrict__ x, const float* __restrict__ gw) {
    __shared__ float gws[8 * HH];
    int eg = blockIdx.x & 31;
    int tg = blockIdx.x >> 5;
    int tid = threadIdx.x;
    for (int idx = tid; idx < 8 * HH; idx += 256)
        gws[idx] = gw[eg * 8 * HH + idx];
    __syncthreads();
    int warp = tid >> 5, lane = tid & 31;
    for (int tt = warp; tt < 32; tt += 8) {
        int t = tg * 32 + tt;
        float acc[8];
#pragma unroll
        for (int e = 0; e < 8; e++) acc[e] = 0.f;
        for (int h = lane; h < HH; h += 32) {
            float xv = x[t * HH + h];
#pragma unroll
            for (int e = 0; e < 8; e++) acc[e] += xv * gws[e * HH + h];
        }
#pragma unroll
        for (int e = 0; e < 8; e++) {
            float v = acc[e];
#pragma unroll
            for (int s = 16; s > 0; s >>= 1) v += __shfl_xor_sync(0xffffffffu, v, s);
            if (lane == e)
                g_scores[t * EE + eg * 8 + e] = 1.f / (1.f + __expf(-v));
        }
    }
}

// ---------------- kernel: routing (1 block, thread = token) ----------------
__global__ void k_route(const float* __restrict__ e_bias) {
    int t = threadIdx.x;
    __shared__ float s_bias[EE];
    __shared__ int s_cnt[EE];
    __shared__ int s_ofs[EE];
    s_bias[t] = e_bias[t];
    s_cnt[t] = 0;
    __syncthreads();
    const float* srow = g_scores + t * EE;

    float gsum[8];
#pragma unroll
    for (int g = 0; g < 8; g++) {
        float m1 = -1e30f, m2 = -1e30f;
        for (int j = 0; j < 32; j++) {
            float v = srow[g * 32 + j] + s_bias[g * 32 + j];
            if (v > m1) { m2 = m1; m1 = v; }
            else if (v > m2) { m2 = v; }
        }
        gsum[g] = m1 + m2;
    }
    unsigned gmask = 0;
    for (int it = 0; it < 4; it++) {
        float best = -1e30f; int bi = 0;
#pragma unroll
        for (int g = 0; g < 8; g++)
            if (!((gmask >> g) & 1u) && gsum[g] > best) { best = gsum[g]; bi = g; }
        gmask |= 1u << bi;
    }
    float bv[8]; int bidx[8];
#pragma unroll
    for (int k = 0; k < 8; k++) { bv[k] = -1e30f; bidx[k] = -1; }
    for (int g = 0; g < 8; g++) {
        if (!((gmask >> g) & 1u)) continue;
        for (int j = 0; j < 32; j++) {
            int e = g * 32 + j;
            float v = srow[e] + s_bias[e];
            if (v > bv[7]) {
#pragma unroll
                for (int k = 7; k > 0; k--) {
                    bool sh = v > bv[k - 1];
                    bool ins = (v > bv[k]) && !sh;
                    float nv = sh ? bv[k - 1] : (ins ? v : bv[k]);
                    int   ni = sh ? bidx[k - 1] : (ins ? e : bidx[k]);
                    bv[k] = nv; bidx[k] = ni;
                }
                if (v > bv[0]) { bv[0] = v; bidx[0] = e; }
            }
        }
    }
    float w[8]; float wsum = 0.f;
#pragma unroll
    for (int k = 0; k < 8; k++) { w[k] = srow[bidx[k]]; wsum += w[k]; }
    float scl = 2.5f / (wsum + 1e-20f);
#pragma unroll
    for (int k = 0; k < 8; k++) {
        w[k] *= scl;
        atomicAdd(&s_cnt[bidx[k]], 1);
    }
    __syncthreads();
    int base = 0;
    for (int e = 0; e < t; e++) base += s_cnt[e];
    s_ofs[t] = base;
    g_base[t] = base;
    g_cnt[t] = s_cnt[t];
    __syncthreads();
#pragma unroll
    for (int k = 0; k < 8; k++) {
        int slot = atomicAdd(&s_ofs[bidx[k]], 1);
        g_pair_tok[slot] = t;
        g_pair_w[slot] = w[k];
    }
}

// ---------------- mlp1 tile (scalar FFMA, float4 smem loads) ----------------
// 256 threads; thread owns column i = tid. Accumulate over all h with 4-h steps,
// weights prefetched one step ahead (8+8 float regs), x from smem via LDS.128.
template <int TT>
__device__ __forceinline__ void mlp1_tile(
    const float* __restrict__ x,
    const float* __restrict__ wg, const float* __restrict__ wu,
    const int* s_toks, int nt, float* __restrict__ act_base, float4* xs4)
{
    const int tid = threadIdx.x;
    float ag[TT], au[TT];
#pragma unroll
    for (int t2 = 0; t2 < TT; t2++) { ag[t2] = 0.f; au[t2] = 0.f; }

    float wa[2][4], wb[2][4];
#pragma unroll
    for (int u = 0; u < 4; u++) {           // prologue: step 0 weights
        wa[0][u] = wg[u * II + tid];
        wb[0][u] = wu[u * II + tid];
    }

    // 256 steps of 4 h; restage x every 64 steps (256 h)
#pragma unroll 1
    for (int s = 0; s < 256; s++) {
        if ((s & 63) == 0) {
            int h0 = (s >> 6) * 256;
            __syncthreads();
            for (int idx = tid; idx < TT * 64; idx += 256) {
                int t2 = idx >> 6;
                int hq = idx & 63;
                float4 v = make_float4(0.f, 0.f, 0.f, 0.f);
                if (t2 < nt)
                    v = *(const float4*)(x + s_toks[t2] * HH + h0 + hq * 4);
                xs4[idx] = v;
            }
            __syncthreads();
        }
        const int cur = s & 1, nxt = cur ^ 1;
        if (s + 1 < 256) {
            int hg = (s + 1) * 4;
#pragma unroll
            for (int u = 0; u < 4; u++) {
                wa[nxt][u] = wg[(hg + u) * II + tid];
                wb[nxt][u] = wu[(hg + u) * II + tid];
            }
        }
        const int hl = s & 63;
#pragma unroll
        for (int t2 = 0; t2 < TT; t2++) {
            float4 xv = xs4[t2 * 64 + hl];
            ag[t2] += xv.x * wa[cur][0]; au[t2] += xv.x * wb[cur][0];
            ag[t2] += xv.y * wa[cur][1]; au[t2] += xv.y * wb[cur][1];
            ag[t2] += xv.z * wa[cur][2]; au[t2] += xv.z * wb[cur][2];
            ag[t2] += xv.w * wa[cur][3]; au[t2] += xv.w * wb[cur][3];
        }
    }
#pragma unroll
    for (int t2 = 0; t2 < TT; t2++) {
        if (t2 < nt) {
            float g = ag[t2];
            float a = g / (1.f + __expf(-g)) * au[t2];
            act_base[(size_t)t2 * II + tid] = a;
        }
    }
}

// grid.x = EE (tile 0) + 16 shared + EE (tile 1); 256 threads
__global__ void __launch_bounds__(256, 3) k_mlp1(
    const float* __restrict__ x,
    const float* __restrict__ wgate, const float* __restrict__ wup,
    const float* __restrict__ swg, const float* __restrict__ swu)
{
    __shared__ float4 xs4[16 * 64];     // 16 KB
    __shared__ int s_toks[16];
    int b = blockIdx.x;
    if (b < EE || b >= EE + 16) {
        int e    = (b < EE) ? b : (b - EE - 16);
        int off0 = (b < EE) ? 0 : 16;
        int cnt = g_cnt[e];
        if (off0 >= cnt) return;
        int base = g_base[e];
        const float* wg = wgate + (size_t)e * HH * II;
        const float* wu = wup   + (size_t)e * HH * II;
        for (int off = off0; off < cnt; off += 32) {
            int nt = min(cnt - off, 16);
            __syncthreads();
            if (threadIdx.x < nt)
                s_toks[threadIdx.x] = g_pair_tok[base + off + threadIdx.x];
            float* act_base = g_act + (size_t)(base + off) * II;
            if (nt <= 8) mlp1_tile<8>(x, wg, wu, s_toks, nt, act_base, xs4);
            else         mlp1_tile<16>(x, wg, wu, s_toks, nt, act_base, xs4);
        }
    } else {
        int j = b - EE;
        if (threadIdx.x < 16) s_toks[threadIdx.x] = j * 16 + threadIdx.x;
        __syncthreads();
        mlp1_tile<16>(x, swg, swu, s_toks, 16, g_act_sh + (size_t)j * 16 * II, xs4);
    }
}

// ---------------- down tile (scalar FFMA, float4 smem loads) ----------------
// 256 threads; thread owns h column = chunk*256 + tid. 64 steps of 4 i.
template <int TT>
__device__ __forceinline__ void down_tile(
    const float* __restrict__ wd, int hcol,
    const int* s_toks, const float* s_w, int nt,
    float* __restrict__ out, const float4* acts4)
{
    float acc[TT];
#pragma unroll
    for (int t2 = 0; t2 < TT; t2++) acc[t2] = 0.f;
    float wv[2][4];
#pragma unroll
    for (int u = 0; u < 4; u++) wv[0][u] = wd[(size_t)u * HH + hcol];
#pragma unroll 1
    for (int s = 0; s < 64; s++) {
        const int cur = s & 1, nxt = cur ^ 1;
        if (s + 1 < 64) {
#pragma unroll
            for (int u = 0; u < 4; u++)
                wv[nxt][u] = wd[(size_t)((s + 1) * 4 + u) * HH + hcol];
        }
#pragma unroll
        for (int t2 = 0; t2 < TT; t2++) {
            float4 av = acts4[t2 * 64 + s];
            acc[t2] += av.x * wv[cur][0];
            acc[t2] += av.y * wv[cur][1];
            acc[t2] += av.z * wv[cur][2];
            acc[t2] += av.w * wv[cur][3];
        }
    }
#pragma unroll
    for (int t2 = 0; t2 < TT; t2++) {
        if (t2 < nt)
            atomicAdd(out + (size_t)s_toks[t2] * HH + hcol, s_w[t2] * acc[t2]);
    }
}

// grid: (EE tile0 + 16 shared + EE tile1) x 4 h-chunks; 256 threads
__global__ void __launch_bounds__(256, 3) k_down(
    const float* __restrict__ wdown, const float* __restrict__ swd,
    float* __restrict__ out)
{
    __shared__ float4 acts4[16 * 64];   // 16 KB
    __shared__ int s_toks[16];
    __shared__ float s_w[16];
    int b = blockIdx.x;
    int hcol = blockIdx.y * 256 + threadIdx.x;
    if (b < EE || b >= EE + 16) {
        int e    = (b < EE) ? b : (b - EE - 16);
        int off0 = (b < EE) ? 0 : 16;
        int cnt = g_cnt[e];
        if (off0 >= cnt) return;
        int base = g_base[e];
        const float* wd = wdown + (size_t)e * II * HH;
        for (int off = off0; off < cnt; off += 32) {
            int nt = min(cnt - off, 16);
            __syncthreads();
            if (threadIdx.x < nt) {
                s_toks[threadIdx.x] = g_pair_tok[base + off + threadIdx.x];
                s_w[threadIdx.x]    = g_pair_w[base + off + threadIdx.x];
            }
            for (int idx = threadIdx.x; idx < 16 * 64; idx += 256) {
                int t2 = idx >> 6, iq = idx & 63;
                float4 v = make_float4(0.f, 0.f, 0.f, 0.f);
                if (t2 < nt)
                    v = *(const float4*)(g_act + (size_t)(base + off + t2) * II + iq * 4);
                acts4[idx] = v;
            }
            __syncthreads();
            if (nt <= 8) down_tile<8>(wd, hcol, s_toks, s_w, nt, out, acts4);
            else         down_tile<16>(wd, hcol, s_toks, s_w, nt, out, acts4);
        }
    } else {
        int j = b - EE;
        if (threadIdx.x < 16) {
            s_toks[threadIdx.x] = j * 16 + threadIdx.x;
            s_w[threadIdx.x] = 1.0f;
        }
        for (int idx = threadIdx.x; idx < 16 * 64; idx += 256) {
            int t2 = idx >> 6, iq = idx & 63;
            acts4[idx] = *(const float4*)(g_act_sh + (size_t)(j * 16 + t2) * II + iq * 4);
        }
        __syncthreads();
        down_tile<16>(swd, hcol, s_toks, s_w, 16, out, acts4);
    }
}

// ---------------- launch ----------------
extern "C" void kernel_launch(void* const* d_in, const int* in_sizes, int n_in,
                              void* d_out, int out_size)
{
    const float* x       = (const float*)d_in[0];  // [1,1,T,H]
    const float* gate_w  = (const float*)d_in[1];  // [E,H]
    const float* e_bias  = (const float*)d_in[2];  // [E]
    const float* w_gate  = (const float*)d_in[3];  // [E,H,I]
    const float* w_up    = (const float*)d_in[4];  // [E,H,I]
    const float* w_down  = (const float*)d_in[5];  // [E,I,H]
    const float* sw_gate = (const float*)d_in[6];  // [H,I]
    const float* sw_up   = (const float*)d_in[7];  // [H,I]
    const float* sw_down = (const float*)d_in[8];  // [I,H]
    float* out = (float*)d_out;                    // [1,1,T,H] fp32

    k_zero<<<(TT_T * HH + 255) / 256, 256>>>(out, TT_T * HH);
    k_gate<<<256, 256>>>(x, gate_w);
    k_route<<<1, 256>>>(e_bias);
    k_mlp1<<<EE * 2 + 16, 256>>>(x, w_gate, w_up, sw_gate, sw_up);
    k_down<<<dim3(EE * 2 + 16, 4), 256>>>(w_down, sw_down, out);
}

// round 5
// speedup vs baseline: 1.9837x; 1.5584x over previous
#include <cuda_runtime.h>
#include <cstdint>
#include <cstddef>

#define TT_T 256      // tokens
#define HH 1024       // hidden
#define EE 256        // experts
#define II 256        // intermediate
#define NPAIR 2048    // T * top_k

typedef unsigned long long u64;

// ---------------- scratch (device globals; no allocations allowed) ----------------
__device__ float g_scores[TT_T * EE];
__device__ int   g_cnt[EE];
__device__ int   g_base[EE];
__device__ int   g_pair_tok[NPAIR];
__device__ float g_pair_w[NPAIR];
__device__ float g_act[NPAIR * II];          // routed silu(h1)*h3
__device__ float g_act_sh[TT_T * II];        // shared-expert silu(h1)*h3

// ---------------- f32x2 / async helpers ----------------
__device__ __forceinline__ u64 fma2(u64 a, u64 b, u64 c) {
    u64 d;
    asm("fma.rn.f32x2 %0, %1, %2, %3;" : "=l"(d) : "l"(a), "l"(b), "l"(c));
    return d;
}
__device__ __forceinline__ u64 pack2(float x, float y) {
    u64 r;
    asm("mov.b64 %0, {%1, %2};" : "=l"(r) : "f"(x), "f"(y));
    return r;
}
__device__ __forceinline__ float2 unpack2(u64 v) {
    float2 r;
    asm("mov.b64 {%0, %1}, %2;" : "=f"(r.x), "=f"(r.y) : "l"(v));
    return r;
}
__device__ __forceinline__ unsigned smem_u32(const void* p) {
    return (unsigned)__cvta_generic_to_shared(p);
}
__device__ __forceinline__ void cp16(unsigned dst, const void* src) {
    asm volatile("cp.async.cg.shared.global [%0], [%1], 16;\n" :: "r"(dst), "l"(src));
}
__device__ __forceinline__ void cp_commit() { asm volatile("cp.async.commit_group;\n"); }
template <int N>
__device__ __forceinline__ void cp_wait() { asm volatile("cp.async.wait_group %0;\n" :: "n"(N)); }

// ---------------- kernel: zero output ----------------
__global__ void k_zero(float* __restrict__ out, int n) {
    int i = blockIdx.x * blockDim.x + threadIdx.x;
    if (i < n) out[i] = 0.f;
}

// ---------------- kernel: gate scores = sigmoid(x @ gate_w^T) ----------------
__global__ void k_gate(const float* __restrict__ x, const float* __restrict__ gw) {
    __shared__ float gws[8 * HH];
    int eg = blockIdx.x & 31;
    int tg = blockIdx.x >> 5;
    int tid = threadIdx.x;
    for (int idx = tid; idx < 8 * HH; idx += 256)
        gws[idx] = gw[eg * 8 * HH + idx];
    __syncthreads();
    int warp = tid >> 5, lane = tid & 31;
    for (int tt = warp; tt < 32; tt += 8) {
        int t = tg * 32 + tt;
        float acc[8];
#pragma unroll
        for (int e = 0; e < 8; e++) acc[e] = 0.f;
        for (int h = lane; h < HH; h += 32) {
            float xv = x[t * HH + h];
#pragma unroll
            for (int e = 0; e < 8; e++) acc[e] += xv * gws[e * HH + h];
        }
#pragma unroll
        for (int e = 0; e < 8; e++) {
            float v = acc[e];
#pragma unroll
            for (int s = 16; s > 0; s >>= 1) v += __shfl_xor_sync(0xffffffffu, v, s);
            if (lane == e)
                g_scores[t * EE + eg * 8 + e] = 1.f / (1.f + __expf(-v));
        }
    }
}

// ---------------- kernel: routing (1 block, thread = token) ----------------
__global__ void k_route(const float* __restrict__ e_bias) {
    int t = threadIdx.x;
    __shared__ float s_bias[EE];
    __shared__ int s_cnt[EE];
    __shared__ int s_ofs[EE];
    s_bias[t] = e_bias[t];
    s_cnt[t] = 0;
    __syncthreads();
    const float* srow = g_scores + t * EE;

    float gsum[8];
#pragma unroll
    for (int g = 0; g < 8; g++) {
        float m1 = -1e30f, m2 = -1e30f;
        for (int j = 0; j < 32; j++) {
            float v = srow[g * 32 + j] + s_bias[g * 32 + j];
            if (v > m1) { m2 = m1; m1 = v; }
            else if (v > m2) { m2 = v; }
        }
        gsum[g] = m1 + m2;
    }
    unsigned gmask = 0;
    for (int it = 0; it < 4; it++) {
        float best = -1e30f; int bi = 0;
#pragma unroll
        for (int g = 0; g < 8; g++)
            if (!((gmask >> g) & 1u) && gsum[g] > best) { best = gsum[g]; bi = g; }
        gmask |= 1u << bi;
    }
    float bv[8]; int bidx[8];
#pragma unroll
    for (int k = 0; k < 8; k++) { bv[k] = -1e30f; bidx[k] = -1; }
    for (int g = 0; g < 8; g++) {
        if (!((gmask >> g) & 1u)) continue;
        for (int j = 0; j < 32; j++) {
            int e = g * 32 + j;
            float v = srow[e] + s_bias[e];
            if (v > bv[7]) {
#pragma unroll
                for (int k = 7; k > 0; k--) {
                    bool sh = v > bv[k - 1];
                    bool ins = (v > bv[k]) && !sh;
                    float nv = sh ? bv[k - 1] : (ins ? v : bv[k]);
                    int   ni = sh ? bidx[k - 1] : (ins ? e : bidx[k]);
                    bv[k] = nv; bidx[k] = ni;
                }
                if (v > bv[0]) { bv[0] = v; bidx[0] = e; }
            }
        }
    }
    float w[8]; float wsum = 0.f;
#pragma unroll
    for (int k = 0; k < 8; k++) { w[k] = srow[bidx[k]]; wsum += w[k]; }
    float scl = 2.5f / (wsum + 1e-20f);
#pragma unroll
    for (int k = 0; k < 8; k++) {
        w[k] *= scl;
        atomicAdd(&s_cnt[bidx[k]], 1);
    }
    __syncthreads();
    int base = 0;
    for (int e = 0; e < t; e++) base += s_cnt[e];
    s_ofs[t] = base;
    g_base[t] = base;
    g_cnt[t] = s_cnt[t];
    __syncthreads();
#pragma unroll
    for (int k = 0; k < 8; k++) {
        int slot = atomicAdd(&s_ofs[bidx[k]], 1);
        g_pair_tok[slot] = t;
        g_pair_w[slot] = w[k];
    }
}

// ================= mlp1: token-paired f32x2, cp.async warp-sliced ring =================
// thread owns column i = tid; acc ag/au[8] = token pairs. ws[4][2][4][II] stage ring,
// each warp copies+consumes only its own 32 columns. xs[p][h] token-paired x chunk.

__device__ __forceinline__ void mlp1_issue(
    const float* __restrict__ wg, const float* __restrict__ wu,
    float (*ws)[2][4][II], int st, int hq, int wrp, int lane)
{
    int h = lane >> 3;
    int col = wrp * 32 + (lane & 7) * 4;
    cp16(smem_u32(&ws[st][0][h][col]), wg + (hq * 4 + h) * II + col);
    cp16(smem_u32(&ws[st][1][h][col]), wu + (hq * 4 + h) * II + col);
    cp_commit();
}

__device__ __forceinline__ void mlp1_tile(
    const float* __restrict__ x,
    const float* __restrict__ wg, const float* __restrict__ wu,
    const int* s_toks, int nt, float* __restrict__ act_base,
    float (*ws)[2][4][II], u64 (*xs)[256])
{
    const int tid = threadIdx.x;
    const int lane = tid & 31, wrp = tid >> 5;
    cp_wait<0>();
    __syncwarp();
    u64 ag[8], au[8];
#pragma unroll
    for (int p = 0; p < 8; p++) { ag[p] = 0ull; au[p] = 0ull; }

    mlp1_issue(wg, wu, ws, 0, 0, wrp, lane);
    mlp1_issue(wg, wu, ws, 1, 1, wrp, lane);
    mlp1_issue(wg, wu, ws, 2, 2, wrp, lane);

#pragma unroll 1
    for (int s = 0; s < 256; s++) {
        if ((s & 63) == 0) {
            int h0 = (s >> 6) << 8;
            __syncthreads();
            for (int idx = tid; idx < 1024; idx += 256) {
                int t2 = idx >> 6, hq = idx & 63;
                float4 v = make_float4(0.f, 0.f, 0.f, 0.f);
                if (t2 < nt) v = *(const float4*)(x + s_toks[t2] * HH + h0 + hq * 4);
                float* bp = (float*)&xs[t2 >> 1][hq * 4];
                int q = t2 & 1;
                bp[0 + q] = v.x; bp[2 + q] = v.y; bp[4 + q] = v.z; bp[6 + q] = v.w;
            }
            __syncthreads();
        }
        if (s + 3 < 256) mlp1_issue(wg, wu, ws, (s + 3) & 3, s + 3, wrp, lane);
        else cp_commit();
        cp_wait<3>();
        __syncwarp();
        const int st = s & 3;
        u64 wgd[4], wud[4];
#pragma unroll
        for (int j = 0; j < 4; j++) {
            float a = ws[st][0][j][tid]; wgd[j] = pack2(a, a);
            float b = ws[st][1][j][tid]; wud[j] = pack2(b, b);
        }
        const int hl = (s & 63) * 4;
#pragma unroll
        for (int p = 0; p < 8; p++) {
            ulonglong2 xa = *(const ulonglong2*)&xs[p][hl];
            ulonglong2 xb = *(const ulonglong2*)&xs[p][hl + 2];
            ag[p] = fma2(xa.x, wgd[0], ag[p]); au[p] = fma2(xa.x, wud[0], au[p]);
            ag[p] = fma2(xa.y, wgd[1], ag[p]); au[p] = fma2(xa.y, wud[1], au[p]);
            ag[p] = fma2(xb.x, wgd[2], ag[p]); au[p] = fma2(xb.x, wud[2], au[p]);
            ag[p] = fma2(xb.y, wgd[3], ag[p]); au[p] = fma2(xb.y, wud[3], au[p]);
        }
    }
#pragma unroll
    for (int p = 0; p < 8; p++) {
        float2 g = unpack2(ag[p]);
        float2 u = unpack2(au[p]);
        int t0 = 2 * p, t1 = 2 * p + 1;
        if (t0 < nt) act_base[(size_t)t0 * II + tid] = g.x / (1.f + __expf(-g.x)) * u.x;
        if (t1 < nt) act_base[(size_t)t1 * II + tid] = g.y / (1.f + __expf(-g.y)) * u.y;
    }
}

__global__ void __launch_bounds__(256, 3) k_mlp1(
    const float* __restrict__ x,
    const float* __restrict__ wgate, const float* __restrict__ wup,
    const float* __restrict__ swg, const float* __restrict__ swu)
{
    __shared__ float ws[4][2][4][II];   // 32 KB weight ring
    __shared__ u64 xs[8][256];          // 16 KB token-paired x chunk
    __shared__ int s_toks[16];
    int b = blockIdx.x;
    if (b < EE || b >= EE + 16) {
        int e    = (b < EE) ? b : (b - EE - 16);
        int off0 = (b < EE) ? 0 : 16;
        int cnt = g_cnt[e];
        if (off0 >= cnt) return;
        int base = g_base[e];
        const float* wg = wgate + (size_t)e * HH * II;
        const float* wu = wup   + (size_t)e * HH * II;
        for (int off = off0; off < cnt; off += 32) {
            int nt = min(cnt - off, 16);
            if (threadIdx.x < nt)
                s_toks[threadIdx.x] = g_pair_tok[base + off + threadIdx.x];
            mlp1_tile(x, wg, wu, s_toks, nt, g_act + (size_t)(base + off) * II, ws, xs);
        }
    } else {
        int j = b - EE;
        if (threadIdx.x < 16) s_toks[threadIdx.x] = j * 16 + threadIdx.x;
        mlp1_tile(x, swg, swu, s_toks, 16, g_act_sh + (size_t)j * 16 * II, ws, xs);
    }
}

// ================= down: token-paired f32x2, cp.async warp-sliced ring =================
// thread owns h column = hc*256 + tid; acc[8] token pairs over i.

__device__ __forceinline__ void down_issue(
    const float* __restrict__ wdc, float (*ws2)[4][256],
    int st, int iq, int wrp, int lane)
{
    int i = lane >> 3;
    int col = wrp * 32 + (lane & 7) * 4;
    cp16(smem_u32(&ws2[st][i][col]), wdc + (size_t)(iq * 4 + i) * HH + col);
    cp_commit();
}

__device__ __forceinline__ void down_tile(
    const float* __restrict__ wdc,            // wd + hc*256
    const int* s_toks, const float* s_w, int nt,
    float* __restrict__ outc,                 // out + hc*256
    u64 (*as4)[256], float (*ws2)[4][256])
{
    const int tid = threadIdx.x;
    const int lane = tid & 31, wrp = tid >> 5;
    cp_wait<0>();
    __syncwarp();
    u64 acc[8];
#pragma unroll
    for (int p = 0; p < 8; p++) acc[p] = 0ull;

    down_issue(wdc, ws2, 0, 0, wrp, lane);
    down_issue(wdc, ws2, 1, 1, wrp, lane);
    down_issue(wdc, ws2, 2, 2, wrp, lane);

#pragma unroll 1
    for (int s = 0; s < 64; s++) {
        if (s + 3 < 64) down_issue(wdc, ws2, (s + 3) & 3, s + 3, wrp, lane);
        else cp_commit();
        cp_wait<3>();
        __syncwarp();
        const int st = s & 3;
        u64 wdv[4];
#pragma unroll
        for (int j = 0; j < 4; j++) {
            float f = ws2[st][j][tid]; wdv[j] = pack2(f, f);
        }
        const int il = s * 4;
#pragma unroll
        for (int p = 0; p < 8; p++) {
            ulonglong2 aa = *(const ulonglong2*)&as4[p][il];
            ulonglong2 ab = *(const ulonglong2*)&as4[p][il + 2];
            acc[p] = fma2(aa.x, wdv[0], acc[p]);
            acc[p] = fma2(aa.y, wdv[1], acc[p]);
            acc[p] = fma2(ab.x, wdv[2], acc[p]);
            acc[p] = fma2(ab.y, wdv[3], acc[p]);
        }
    }
#pragma unroll
    for (int p = 0; p < 8; p++) {
        float2 r = unpack2(acc[p]);
        int t0 = 2 * p, t1 = 2 * p + 1;
        if (t0 < nt) atomicAdd(outc + (size_t)s_toks[t0] * HH + tid, s_w[t0] * r.x);
        if (t1 < nt) atomicAdd(outc + (size_t)s_toks[t1] * HH + tid, s_w[t1] * r.y);
    }
}

__global__ void __launch_bounds__(256, 4) k_down(
    const float* __restrict__ wdown, const float* __restrict__ swd,
    float* __restrict__ out)
{
    __shared__ float ws2[4][4][256];    // 16 KB weight ring
    __shared__ u64 as4[8][256];         // 16 KB token-paired act
    __shared__ int s_toks[16];
    __shared__ float s_w[16];
    int b = blockIdx.x;
    int hc = blockIdx.y;
    if (b < EE || b >= EE + 16) {
        int e    = (b < EE) ? b : (b - EE - 16);
        int off0 = (b < EE) ? 0 : 16;
        int cnt = g_cnt[e];
        if (off0 >= cnt) return;
        int base = g_base[e];
        const float* wdc = wdown + (size_t)e * II * HH + hc * 256;
        for (int off = off0; off < cnt; off += 32) {
            int nt = min(cnt - off, 16);
            __syncthreads();
            if (threadIdx.x < nt) {
                s_toks[threadIdx.x] = g_pair_tok[base + off + threadIdx.x];
                s_w[threadIdx.x]    = g_pair_w[base + off + threadIdx.x];
            }
#pragma unroll
            for (int p = 0; p < 8; p++) {
                int t0 = 2 * p, t1 = 2 * p + 1;
                float v0 = (t0 < nt) ? g_act[(size_t)(base + off + t0) * II + threadIdx.x] : 0.f;
                float v1 = (t1 < nt) ? g_act[(size_t)(base + off + t1) * II + threadIdx.x] : 0.f;
                as4[p][threadIdx.x] = pack2(v0, v1);
            }
            __syncthreads();
            down_tile(wdc, s_toks, s_w, nt, out + hc * 256, as4, ws2);
        }
    } else {
        int j = b - EE;
        if (threadIdx.x < 16) {
            s_toks[threadIdx.x] = j * 16 + threadIdx.x;
            s_w[threadIdx.x] = 1.0f;
        }
#pragma unroll
        for (int p = 0; p < 8; p++) {
            float v0 = g_act_sh[(size_t)(j * 16 + 2 * p)     * II + threadIdx.x];
            float v1 = g_act_sh[(size_t)(j * 16 + 2 * p + 1) * II + threadIdx.x];
            as4[p][threadIdx.x] = pack2(v0, v1);
        }
        __syncthreads();
        down_tile(swd + hc * 256, s_toks, s_w, 16, out + hc * 256, as4, ws2);
    }
}

// ---------------- launch ----------------
extern "C" void kernel_launch(void* const* d_in, const int* in_sizes, int n_in,
                              void* d_out, int out_size)
{
    const float* x       = (const float*)d_in[0];  // [1,1,T,H]
    const float* gate_w  = (const float*)d_in[1];  // [E,H]
    const float* e_bias  = (const float*)d_in[2];  // [E]
    const float* w_gate  = (const float*)d_in[3];  // [E,H,I]
    const float* w_up    = (const float*)d_in[4];  // [E,H,I]
    const float* w_down  = (const float*)d_in[5];  // [E,I,H]
    const float* sw_gate = (const float*)d_in[6];  // [H,I]
    const float* sw_up   = (const float*)d_in[7];  // [H,I]
    const float* sw_down = (const float*)d_in[8];  // [I,H]
    float* out = (float*)d_out;                    // [1,1,T,H] fp32

    k_zero<<<(TT_T * HH + 255) / 256, 256>>>(out, TT_T * HH);
    k_gate<<<256, 256>>>(x, gate_w);
    k_route<<<1, 256>>>(e_bias);
    k_mlp1<<<EE * 2 + 16, 256>>>(x, w_gate, w_up, sw_gate, sw_up);
    k_down<<<dim3(EE * 2 + 16, 4), 256>>>(w_down, sw_down, out);
}